// round 2
// baseline (speedup 1.0000x reference)
#include <cuda_runtime.h>
#include <math.h>

// Problem constants (fixed by the dataset)
#define N_NODES 40000
#define N_PAD   40064            // padded to multiple of 128 for guard-free GEMM loads
#define N_EDGES 1280000
#define HIDN 128
#define NG 50
#define NL 3
#define TT 8192                  // distance-table resolution

#define GDELTA (10.0f/49.0f)     // gaussian offset spacing
#define DMAX 12.8f               // beyond this, all gaussians underflow -> W == 0
#define HSTEP (DMAX/(float)(TT-1))
#define INV_H ((float)(TT-1)/DMAX)
#define UCLAMP ((float)(TT-1) - 1e-3f)
#define LOG2_CONST 0.69314718055994531f

// ---------------- device scratch (no allocations allowed) ----------------
__device__ float g_table[NL*TT*HIDN];   // W(d) lookup per layer  (12.6 MB)
__device__ float g_hid[NL*TT*HIDN];     // intermediate ssp(attr@w1+b1)
__device__ float g_rowC[TT];            // cosine cutoff per table point
__device__ float g_h[N_PAD*HIDN];
__device__ float g_x[N_PAD*HIDN];
__device__ float g_tmp[N_PAD*HIDN];
__device__ float g_u[N_EDGES];          // per-edge table coordinate
__device__ int   g_deg[N_NODES];
__device__ int   g_cursor[N_NODES];
__device__ int   g_offs[N_NODES+1];
__device__ int   g_crow[N_EDGES];       // CSR: source node per slot
__device__ float g_cu[N_EDGES];         // CSR: table coord per slot

__device__ __forceinline__ float sspf(float x){
    // softplus(x) - log(2), numerically stable
    float sp = (x > 0.f) ? (x + log1pf(expf(-x))) : log1pf(expf(x));
    return sp - LOG2_CONST;
}

// ---------------- small setup kernels ----------------
__global__ void zero_deg_k(int n){
    int i = blockIdx.x*blockDim.x + threadIdx.x;
    if (i < n) g_deg[i] = 0;
}

// per-edge distance -> table coordinate u; count in-degree (skip edges with W==0)
__global__ void dist_k(const int* __restrict__ ei, const float* __restrict__ pos, int E){
    int e = blockIdx.x*blockDim.x + threadIdx.x;
    if (e >= E) return;
    int r = ei[e], c = ei[E+e];
    float dx = pos[3*r]   - pos[3*c];
    float dy = pos[3*r+1] - pos[3*c+1];
    float dz = pos[3*r+2] - pos[3*c+2];
    float d = sqrtf(dx*dx + dy*dy + dz*dz);
    float u = d * INV_H;
    if (u < UCLAMP){
        g_u[e] = u;
        atomicAdd(&g_deg[c], 1);
    } else {
        g_u[e] = UCLAMP;   // marker: skip (true W ~ 1e-41)
    }
}

// single-block exclusive scan of g_deg -> g_offs, g_cursor
__global__ void scan_k(int n){
    __shared__ int sh[1024];
    int t = threadIdx.x;
    int chunk = (n + 1023) / 1024;
    int start = t*chunk;
    int end   = min(start + chunk, n);
    int s = 0;
    for (int i = start; i < end; i++) s += g_deg[i];
    sh[t] = s;
    __syncthreads();
    for (int d = 1; d < 1024; d <<= 1){
        int v = 0;
        if (t >= d) v = sh[t-d];
        __syncthreads();
        sh[t] += v;
        __syncthreads();
    }
    int run = sh[t] - s;    // exclusive prefix of this thread's chunk
    for (int i = start; i < end; i++){
        g_offs[i] = run; g_cursor[i] = run;
        run += g_deg[i];
    }
    if (end == n && start < n) g_offs[n] = run;
}

__global__ void fill_k(const int* __restrict__ ei, int E){
    int e = blockIdx.x*blockDim.x + threadIdx.x;
    if (e >= E) return;
    float u = g_u[e];
    if (u >= UCLAMP) return;
    int c = ei[E+e];
    int slot = atomicAdd(&g_cursor[c], 1);
    g_crow[slot] = ei[e];
    g_cu[slot]   = u;
}

__global__ void embed_k(const int* __restrict__ z, const float* __restrict__ emb, int n){
    int idx = blockIdx.x*blockDim.x + threadIdx.x;
    if (idx >= n*HIDN) return;
    int v = idx >> 7, f = idx & 127;
    g_h[idx] = emb[z[v]*HIDN + f];
}

// ---------------- table build stage 1: ssp(attr(d) @ w1 + b1) ----------------
__global__ __launch_bounds__(128) void hid_k(const float* __restrict__ w1all,
                                             const float* __restrict__ b1all){
    constexpr int PPB = 8;            // table points per block
    constexpr int BPL = TT / PPB;
    int l  = blockIdx.x / BPL;
    int p0 = (blockIdx.x % BPL) * PPB;
    int f  = threadIdx.x;
    __shared__ float w1s[NG*HIDN];
    __shared__ float attr[NG];
    const float* w1 = w1all + (size_t)l*NG*HIDN;
    for (int q = f; q < NG*HIDN; q += 128) w1s[q] = w1[q];
    float b1 = b1all[l*HIDN + f];
    const float GCOEFF = -0.5f/(GDELTA*GDELTA);
    for (int p = 0; p < PPB; p++){
        int pt = p0 + p;
        float d = pt * HSTEP;
        __syncthreads();
        if (f < NG){
            float td = d - (float)f * GDELTA;
            attr[f] = expf(GCOEFF * td * td);
        }
        __syncthreads();
        float s = b1;
#pragma unroll
        for (int g = 0; g < NG; g++) s = fmaf(attr[g], w1s[g*HIDN + f], s);
        g_hid[((size_t)l*TT + pt)*HIDN + f] = sspf(s);
        if (l == 0 && f == 0)
            g_rowC[pt] = 0.5f*(cosf(d * 0.31415926535897931f) + 1.f); // pi/10
    }
}

// ---------------- generic SGEMM: C = f(A[Mx128] @ W[128xBN]) ----------------
template<int BN, bool BIAS, bool ACT, bool RES, bool ROWSCALE>
__global__ __launch_bounds__(256) void gemm_k(
    const float* __restrict__ A, const float* __restrict__ W,
    const float* __restrict__ bias, const float* __restrict__ rowscale,
    float* __restrict__ C, int M)
{
    constexpr int BM = 128, BK = 16, TN = BN/16;
    __shared__ float As[BK][BM];
    __shared__ float Bs[BK][BN];
    int tid = threadIdx.x;
    int tm = tid >> 4, tn = tid & 15;
    int rowBase = blockIdx.x * BM;
    float acc[8][TN];
#pragma unroll
    for (int i = 0; i < 8; i++)
#pragma unroll
        for (int j = 0; j < TN; j++) acc[i][j] = 0.f;

    for (int k0 = 0; k0 < HIDN; k0 += BK){
#pragma unroll
        for (int it = 0; it < 2; it++){
            int q = tid + it*256;        // 512 float4 = 128 rows x 16 cols
            int r = q >> 2, kq = (q & 3) << 2;
            float4 v = *(const float4*)(A + (size_t)(rowBase + r)*HIDN + k0 + kq);
            As[kq+0][r] = v.x; As[kq+1][r] = v.y; As[kq+2][r] = v.z; As[kq+3][r] = v.w;
        }
#pragma unroll
        for (int q = tid; q < BK*BN/4; q += 256){
            int r = q / (BN/4), cq = (q % (BN/4)) * 4;
            *(float4*)&Bs[r][cq] = *(const float4*)(W + (size_t)(k0 + r)*BN + cq);
        }
        __syncthreads();
#pragma unroll
        for (int k = 0; k < BK; k++){
            float a[8], b[TN];
#pragma unroll
            for (int i = 0; i < 8; i += 4) *(float4*)&a[i] = *(float4*)&As[k][tm*8 + i];
#pragma unroll
            for (int j = 0; j < TN; j += 4) *(float4*)&b[j] = *(float4*)&Bs[k][tn*TN + j];
#pragma unroll
            for (int i = 0; i < 8; i++)
#pragma unroll
                for (int j = 0; j < TN; j++) acc[i][j] = fmaf(a[i], b[j], acc[i][j]);
        }
        __syncthreads();
    }
#pragma unroll
    for (int i = 0; i < 8; i++){
        int row = rowBase + tm*8 + i;
        if (row < M){
            float rs = ROWSCALE ? rowscale[row] : 1.0f;
#pragma unroll
            for (int j = 0; j < TN; j++){
                int cc = tn*TN + j;
                float v = acc[i][j];
                if (BIAS) v += bias[cc];
                if (ACT)  v = sspf(v);
                if (ROWSCALE) v *= rs;
                if (RES)  v += C[(size_t)row*BN + cc];
                C[(size_t)row*BN + cc] = v;
            }
        }
    }
}

// ---------------- CSR aggregation: agg[v] = sum_e x[row_e] * lerp(table, u_e) ----------------
__global__ __launch_bounds__(128) void agg_k(const float* __restrict__ table,
                                             const float* __restrict__ x,
                                             float* __restrict__ out)
{
    int v = blockIdx.x, f = threadIdx.x;
    int s = g_offs[v], e = g_offs[v+1];
    float acc = 0.f;
#pragma unroll 2
    for (int k = s; k < e; k++){
        int   r  = g_crow[k];      // broadcast across block
        float u  = g_cu[k];
        int   i  = (int)u;
        float fr = u - (float)i;
        const float* t = table + (size_t)i*HIDN + f;
        float w0 = __ldg(t), w1 = __ldg(t + HIDN);
        acc = fmaf(__ldg(x + (size_t)r*HIDN + f), fmaf(fr, w1 - w0, w0), acc);
    }
    out[(size_t)v*HIDN + f] = acc;
}

// ---------------- launch ----------------
extern "C" void kernel_launch(void* const* d_in, const int* in_sizes, int n_in,
                              void* d_out, int out_size)
{
    const int*   z   = (const int*)  d_in[0];
    const float* pos = (const float*)d_in[1];
    const int*   ei  = (const int*)  d_in[3];
    const float* emb = (const float*)d_in[4];
    const float* mw1 = (const float*)d_in[5];
    const float* mb1 = (const float*)d_in[6];
    const float* mw2 = (const float*)d_in[7];
    const float* mb2 = (const float*)d_in[8];
    const float* cw1 = (const float*)d_in[9];
    const float* cw2 = (const float*)d_in[10];
    const float* cb2 = (const float*)d_in[11];
    const float* lw  = (const float*)d_in[12];
    const float* lb  = (const float*)d_in[13];
    const float* l1w = (const float*)d_in[14];
    const float* l1b = (const float*)d_in[15];
    float* out = (float*)d_out;

    int N = in_sizes[0];
    int E = in_sizes[3] / 2;
    if (N > N_NODES || E > N_EDGES) return;

    float *p_table, *p_hid, *p_rowC, *p_h, *p_x, *p_tmp;
    cudaGetSymbolAddress((void**)&p_table, g_table);
    cudaGetSymbolAddress((void**)&p_hid,   g_hid);
    cudaGetSymbolAddress((void**)&p_rowC,  g_rowC);
    cudaGetSymbolAddress((void**)&p_h,     g_h);
    cudaGetSymbolAddress((void**)&p_x,     g_x);
    cudaGetSymbolAddress((void**)&p_tmp,   g_tmp);

    // CSR + table build (every replay; deterministic)
    zero_deg_k<<<(N+255)/256, 256>>>(N);
    dist_k<<<(E+255)/256, 256>>>(ei, pos, E);
    hid_k<<<NL*(TT/8), 128>>>(mw1, mb1);
    for (int l = 0; l < NL; l++)
        gemm_k<128,true,false,false,true><<<TT/128, 256>>>(
            p_hid + (size_t)l*TT*HIDN, mw2 + (size_t)l*HIDN*HIDN,
            mb2 + l*HIDN, p_rowC, p_table + (size_t)l*TT*HIDN, TT);
    scan_k<<<1, 1024>>>(N);
    fill_k<<<(E+255)/256, 256>>>(ei, E);
    embed_k<<<(N*HIDN+255)/256, 256>>>(z, emb, N);

    int gb = (N + 127) / 128;
    for (int l = 0; l < NL; l++){
        // x = h @ conv_w1[l]
        gemm_k<128,false,false,false,false><<<gb, 256>>>(
            p_h, cw1 + (size_t)l*HIDN*HIDN, nullptr, nullptr, p_x, N);
        // agg = scatter-free CSR aggregation with table-interpolated W
        agg_k<<<N, 128>>>(p_table + (size_t)l*TT*HIDN, p_x, p_tmp);
        // x2 = ssp(agg @ conv_w2[l] + b2)
        gemm_k<128,true,true,false,false><<<gb, 256>>>(
            p_tmp, cw2 + (size_t)l*HIDN*HIDN, cb2 + l*HIDN, nullptr, p_x, N);
        // h += x2 @ lin_w[l] + lin_b[l]
        gemm_k<128,true,false,true,false><<<gb, 256>>>(
            p_x, lw + (size_t)l*HIDN*HIDN, lb + l*HIDN, nullptr, p_h, N);
    }
    // out = ssp(h @ lin1_w + lin1_b)
    gemm_k<64,true,true,false,false><<<gb, 256>>>(p_h, l1w, l1b, nullptr, out, N);
}

// round 3
// speedup vs baseline: 1.1580x; 1.1580x over previous
#include <cuda_runtime.h>
#include <cuda_fp16.h>
#include <math.h>

// Problem constants (fixed by the dataset)
#define N_NODES 40000
#define N_PAD   40064            // padded to multiple of 128 for guard-free GEMM loads
#define N_EDGES 1280000
#define HIDN 128
#define NG 50
#define NL 3
#define TT 8192                  // distance-table resolution

#define GDELTA (10.0f/49.0f)     // gaussian offset spacing
#define DMAX 12.8f               // beyond this, all gaussians underflow -> W == 0
#define HSTEP (DMAX/(float)(TT-1))
#define INV_H ((float)(TT-1)/DMAX)
#define UCLAMP ((float)(TT-1) - 1e-3f)
#define LOG2_CONST 0.69314718055994531f

typedef unsigned long long ull;

// ---------------- device scratch (no allocations allowed) ----------------
__device__ __half g_table_h[NL*TT*HIDN]; // W(d) lookup per layer, fp16 (6.3 MB)
__device__ float g_hid[NL*TT*HIDN];      // intermediate ssp(attr@w1+b1)
__device__ float g_rowC[TT];             // cosine cutoff per table point
__device__ float g_h[N_PAD*HIDN];
__device__ __half g_xh[N_PAD*HIDN];      // x = h@conv_w1, fp16 for aggregation
__device__ float g_x[N_PAD*HIDN];
__device__ float g_tmp[N_PAD*HIDN];
__device__ float g_u[N_EDGES];           // per-edge table coordinate
__device__ int   g_deg[N_NODES];
__device__ int   g_cursor[N_NODES];
__device__ int   g_offs[N_NODES+1];
__device__ int   g_crow[N_EDGES];        // CSR: source node per slot
__device__ float g_cu[N_EDGES];          // CSR: table coord per slot

__device__ __forceinline__ float sspf(float x){
    float sp = (x > 0.f) ? (x + log1pf(expf(-x))) : log1pf(expf(x));
    return sp - LOG2_CONST;
}

// ---- packed f32x2 helpers (ptxas will NOT auto-fuse; PTX-only path) ----
__device__ __forceinline__ ull pack2(float x, float y){
    ull r; asm("mov.b64 %0, {%1, %2};" : "=l"(r) : "f"(x), "f"(y)); return r;
}
__device__ __forceinline__ void unpack2(ull v, float &x, float &y){
    asm("mov.b64 {%0, %1}, %2;" : "=f"(x), "=f"(y) : "l"(v));
}
__device__ __forceinline__ void ffma2(ull &c, ull a, ull b){
    asm("fma.rn.f32x2 %0, %1, %2, %0;" : "+l"(c) : "l"(a), "l"(b));
}

// ---------------- small setup kernels ----------------
__global__ void zero_deg_k(int n){
    int i = blockIdx.x*blockDim.x + threadIdx.x;
    if (i < n) g_deg[i] = 0;
}

__global__ void dist_k(const int* __restrict__ ei, const float* __restrict__ pos, int E){
    int e = blockIdx.x*blockDim.x + threadIdx.x;
    if (e >= E) return;
    int r = ei[e], c = ei[E+e];
    float dx = pos[3*r]   - pos[3*c];
    float dy = pos[3*r+1] - pos[3*c+1];
    float dz = pos[3*r+2] - pos[3*c+2];
    float d = sqrtf(dx*dx + dy*dy + dz*dz);
    float u = d * INV_H;
    if (u < UCLAMP){
        g_u[e] = u;
        atomicAdd(&g_deg[c], 1);
    } else {
        g_u[e] = UCLAMP;   // marker: skip (true W ~ 1e-41)
    }
}

__global__ void scan_k(int n){
    __shared__ int sh[1024];
    int t = threadIdx.x;
    int chunk = (n + 1023) / 1024;
    int start = t*chunk;
    int end   = min(start + chunk, n);
    int s = 0;
    for (int i = start; i < end; i++) s += g_deg[i];
    sh[t] = s;
    __syncthreads();
    for (int d = 1; d < 1024; d <<= 1){
        int v = 0;
        if (t >= d) v = sh[t-d];
        __syncthreads();
        sh[t] += v;
        __syncthreads();
    }
    int run = sh[t] - s;
    for (int i = start; i < end; i++){
        g_offs[i] = run; g_cursor[i] = run;
        run += g_deg[i];
    }
    if (end == n && start < n) g_offs[n] = run;
}

__global__ void fill_k(const int* __restrict__ ei, int E){
    int e = blockIdx.x*blockDim.x + threadIdx.x;
    if (e >= E) return;
    float u = g_u[e];
    if (u >= UCLAMP) return;
    int c = ei[E+e];
    int slot = atomicAdd(&g_cursor[c], 1);
    g_crow[slot] = ei[e];
    g_cu[slot]   = u;
}

__global__ void embed_k(const int* __restrict__ z, const float* __restrict__ emb, int n){
    int idx = blockIdx.x*blockDim.x + threadIdx.x;
    if (idx >= n*HIDN) return;
    int v = idx >> 7, f = idx & 127;
    g_h[idx] = emb[z[v]*HIDN + f];
}

// ---------------- table build stage 1: ssp(attr(d) @ w1 + b1) ----------------
__global__ __launch_bounds__(128) void hid_k(const float* __restrict__ w1all,
                                             const float* __restrict__ b1all){
    constexpr int PPB = 8;
    constexpr int BPL = TT / PPB;
    int l  = blockIdx.x / BPL;
    int p0 = (blockIdx.x % BPL) * PPB;
    int f  = threadIdx.x;
    __shared__ float w1s[NG*HIDN];
    __shared__ float attr[NG];
    const float* w1 = w1all + (size_t)l*NG*HIDN;
    for (int q = f; q < NG*HIDN; q += 128) w1s[q] = w1[q];
    float b1 = b1all[l*HIDN + f];
    const float GCOEFF = -0.5f/(GDELTA*GDELTA);
    for (int p = 0; p < PPB; p++){
        int pt = p0 + p;
        float d = pt * HSTEP;
        __syncthreads();
        if (f < NG){
            float td = d - (float)f * GDELTA;
            attr[f] = expf(GCOEFF * td * td);
        }
        __syncthreads();
        float s = b1;
#pragma unroll
        for (int g = 0; g < NG; g++) s = fmaf(attr[g], w1s[g*HIDN + f], s);
        g_hid[((size_t)l*TT + pt)*HIDN + f] = sspf(s);
        if (l == 0 && f == 0)
            g_rowC[pt] = 0.5f*(cosf(d * 0.31415926535897931f) + 1.f); // pi/10
    }
}

// ---------------- SGEMM with packed f32x2 FMA: C = f(A[Mx128] @ W[128xBN]) ----------------
template<int BN, bool BIAS, bool ACT, bool RES, bool ROWSCALE, bool HOUT>
__global__ __launch_bounds__(256,2) void gemm_k(
    const float* __restrict__ A, const float* __restrict__ W,
    const float* __restrict__ bias, const float* __restrict__ rowscale,
    void* __restrict__ Cv, int M)
{
    constexpr int BM = 128, BK = 16, TN = BN/16;
    __shared__ __align__(16) float As[BK][BM];
    __shared__ __align__(16) float Bs[BK][BN];
    float*  C  = (float*)Cv;
    __half* Ch = (__half*)Cv;
    int tid = threadIdx.x;
    int tm = tid >> 4, tn = tid & 15;
    int rowBase = blockIdx.x * BM;

    // acc[i2][j]: .lo = row 2*i2, .hi = row 2*i2+1, column tn*TN+j
    ull acc[4][TN];
#pragma unroll
    for (int i = 0; i < 4; i++)
#pragma unroll
        for (int j = 0; j < TN; j++) acc[i][j] = 0ull;

    for (int k0 = 0; k0 < HIDN; k0 += BK){
#pragma unroll
        for (int it = 0; it < 2; it++){
            int q = tid + it*256;        // 512 float4 = 128 rows x 16 cols
            int r = q >> 2, kq = (q & 3) << 2;
            float4 v = *(const float4*)(A + (size_t)(rowBase + r)*HIDN + k0 + kq);
            As[kq+0][r] = v.x; As[kq+1][r] = v.y; As[kq+2][r] = v.z; As[kq+3][r] = v.w;
        }
#pragma unroll
        for (int q = tid; q < BK*BN/4; q += 256){
            int r = q / (BN/4), cq = (q % (BN/4)) * 4;
            *(float4*)&Bs[r][cq] = *(const float4*)(W + (size_t)(k0 + r)*BN + cq);
        }
        __syncthreads();
#pragma unroll
        for (int k = 0; k < BK; k++){
            // A row-pairs load directly as 64-bit packed operands
            ull a2[4];
            {
                const ulonglong2* ap = (const ulonglong2*)&As[k][tm*8];
                ulonglong2 v0 = ap[0], v1 = ap[1];
                a2[0] = v0.x; a2[1] = v0.y; a2[2] = v1.x; a2[3] = v1.y;
            }
            float b[TN];
#pragma unroll
            for (int j = 0; j < TN; j += 4) *(float4*)&b[j] = *(float4*)&Bs[k][tn*TN + j];
#pragma unroll
            for (int j = 0; j < TN; j++){
                ull b2 = pack2(b[j], b[j]);
#pragma unroll
                for (int i2 = 0; i2 < 4; i2++) ffma2(acc[i2][j], a2[i2], b2);
            }
        }
        __syncthreads();
    }

#pragma unroll
    for (int i2 = 0; i2 < 4; i2++){
        float vlo[TN], vhi[TN];
#pragma unroll
        for (int j = 0; j < TN; j++) unpack2(acc[i2][j], vlo[j], vhi[j]);
#pragma unroll
        for (int hh = 0; hh < 2; hh++){
            int row = rowBase + tm*8 + 2*i2 + hh;
            if (row < M){
                float rs = ROWSCALE ? rowscale[row] : 1.0f;
#pragma unroll
                for (int j = 0; j < TN; j++){
                    int cc = tn*TN + j;
                    float v = hh ? vhi[j] : vlo[j];
                    if (BIAS) v += bias[cc];
                    if (ACT)  v = sspf(v);
                    if (ROWSCALE) v *= rs;
                    if (HOUT){
                        Ch[(size_t)row*BN + cc] = __float2half(v);
                    } else {
                        if (RES) v += C[(size_t)row*BN + cc];
                        C[(size_t)row*BN + cc] = v;
                    }
                }
            }
        }
    }
}

// ---------------- CSR aggregation (fp16 operands, fp32 accumulate) ----------------
// block = (64 feature-pairs, 4 nodes); agg[v] = sum_e x[row_e] * lerp(table, u_e)
__global__ __launch_bounds__(256) void agg_k(const __half* __restrict__ table,
                                             const __half* __restrict__ xh,
                                             float* __restrict__ out, int N)
{
    int v = blockIdx.x*4 + threadIdx.y;
    if (v >= N) return;
    int f = threadIdx.x;  // 0..63: half2 feature index
    const __half2* tab = (const __half2*)table;
    const __half2* xp  = (const __half2*)xh;
    int s = g_offs[v], e = g_offs[v+1];
    float2 acc = make_float2(0.f, 0.f);
#pragma unroll 4
    for (int k = s; k < e; k++){
        int   r  = g_crow[k];       // uniform within warp
        float u  = g_cu[k];
        int   i  = (int)u;
        float fr = u - (float)i;
        float2 xv = __half22float2(xp[(size_t)r*64 + f]);
        float2 w0 = __half22float2(tab[(size_t)i*64 + f]);
        float2 w1 = __half22float2(tab[(size_t)(i+1)*64 + f]);
        float wa = fmaf(fr, w1.x - w0.x, w0.x);
        float wb = fmaf(fr, w1.y - w0.y, w0.y);
        acc.x = fmaf(xv.x, wa, acc.x);
        acc.y = fmaf(xv.y, wb, acc.y);
    }
    *(float2*)&out[(size_t)v*HIDN + 2*f] = acc;
}

// ---------------- launch ----------------
extern "C" void kernel_launch(void* const* d_in, const int* in_sizes, int n_in,
                              void* d_out, int out_size)
{
    const int*   z   = (const int*)  d_in[0];
    const float* pos = (const float*)d_in[1];
    const int*   ei  = (const int*)  d_in[3];
    const float* emb = (const float*)d_in[4];
    const float* mw1 = (const float*)d_in[5];
    const float* mb1 = (const float*)d_in[6];
    const float* mw2 = (const float*)d_in[7];
    const float* mb2 = (const float*)d_in[8];
    const float* cw1 = (const float*)d_in[9];
    const float* cw2 = (const float*)d_in[10];
    const float* cb2 = (const float*)d_in[11];
    const float* lw  = (const float*)d_in[12];
    const float* lb  = (const float*)d_in[13];
    const float* l1w = (const float*)d_in[14];
    const float* l1b = (const float*)d_in[15];
    float* out = (float*)d_out;

    int N = in_sizes[0];
    int E = in_sizes[3] / 2;
    if (N > N_NODES || E > N_EDGES) return;

    float *p_hid, *p_rowC, *p_h, *p_x, *p_tmp;
    __half *p_tab, *p_xh;
    cudaGetSymbolAddress((void**)&p_tab,  g_table_h);
    cudaGetSymbolAddress((void**)&p_hid,  g_hid);
    cudaGetSymbolAddress((void**)&p_rowC, g_rowC);
    cudaGetSymbolAddress((void**)&p_h,    g_h);
    cudaGetSymbolAddress((void**)&p_xh,   g_xh);
    cudaGetSymbolAddress((void**)&p_x,    g_x);
    cudaGetSymbolAddress((void**)&p_tmp,  g_tmp);

    // CSR + table build (every replay; deterministic)
    zero_deg_k<<<(N+255)/256, 256>>>(N);
    dist_k<<<(E+255)/256, 256>>>(ei, pos, E);
    hid_k<<<NL*(TT/8), 128>>>(mw1, mb1);
    for (int l = 0; l < NL; l++)
        gemm_k<128,true,false,false,true,true><<<TT/128, 256>>>(
            p_hid + (size_t)l*TT*HIDN, mw2 + (size_t)l*HIDN*HIDN,
            mb2 + l*HIDN, p_rowC, p_tab + (size_t)l*TT*HIDN, TT);
    scan_k<<<1, 1024>>>(N);
    fill_k<<<(E+255)/256, 256>>>(ei, E);
    embed_k<<<(N*HIDN+255)/256, 256>>>(z, emb, N);

    int gb = (N + 127) / 128;
    dim3 ablk(64, 4);
    int agrid = (N + 3) / 4;
    for (int l = 0; l < NL; l++){
        // x = h @ conv_w1[l]   (half output for aggregation)
        gemm_k<128,false,false,false,false,true><<<gb, 256>>>(
            p_h, cw1 + (size_t)l*HIDN*HIDN, nullptr, nullptr, p_xh, N);
        // agg = scatter-free CSR aggregation with table-interpolated W
        agg_k<<<agrid, ablk>>>(p_tab + (size_t)l*TT*HIDN, p_xh, p_tmp, N);
        // x2 = ssp(agg @ conv_w2[l] + b2)
        gemm_k<128,true,true,false,false,false><<<gb, 256>>>(
            p_tmp, cw2 + (size_t)l*HIDN*HIDN, cb2 + l*HIDN, nullptr, p_x, N);
        // h += x2 @ lin_w[l] + lin_b[l]
        gemm_k<128,true,false,true,false,false><<<gb, 256>>>(
            p_x, lw + (size_t)l*HIDN*HIDN, lb + l*HIDN, nullptr, p_h, N);
    }
    // out = ssp(h @ lin1_w + lin1_b)
    gemm_k<64,true,true,false,false,false><<<gb, 256>>>(p_h, l1w, l1b, nullptr, out, N);
}